// round 2
// baseline (speedup 1.0000x reference)
#include <cuda_runtime.h>
#include <cstdint>

typedef unsigned long long ull;

#define NB      1024
#define N1      64
#define N2      128
#define DD      256
#define LN_EPS  1e-5f
#define ISCALE  0.0625f     // D^-0.5 = 1/16

// SMEM strides (in floats). 258 => consecutive rows shift banks by 2 (conflict-free
// column access, 8-byte aligned for float2). 132 => conflict-free I stores/loads.
#define S_H 258
#define S_I 132

static constexpr int SH2_OFF     = N1 * S_H;              // 16512 floats
static constexpr int SI_OFF      = SH2_OFF + N2 * S_H;    // 49536 floats
static constexpr int SMEM_FLOATS = SI_OFF + N1 * S_I;     // 57984 floats
static constexpr int SMEM_BYTES  = SMEM_FLOATS * 4;       // 231936 B (<= 232448 max)

// ---- packed fp32x2 helpers (Blackwell FFMA2 path) ----
__device__ __forceinline__ ull fma2(ull a, ull b, ull c) {
    ull d;
    asm("fma.rn.f32x2 %0, %1, %2, %3;" : "=l"(d) : "l"(a), "l"(b), "l"(c));
    return d;
}
__device__ __forceinline__ ull dup2(float x) {
    unsigned xu = __float_as_uint(x);
    ull r;
    asm("mov.b64 %0, {%1, %1};" : "=l"(r) : "r"(xu));
    return r;
}
__device__ __forceinline__ void unpack2(ull v, float& lo, float& hi) {
    unsigned a, b;
    asm("mov.b64 {%0, %1}, %2;" : "=r"(a), "=r"(b) : "l"(v));
    lo = __uint_as_float(a);
    hi = __uint_as_float(b);
}
__device__ __forceinline__ ull lds64(const float* p) {
    return *reinterpret_cast<const ull*>(p);
}

__global__ void __launch_bounds__(256, 1)
interaction_kernel(const float* __restrict__ h1g, const float* __restrict__ h2g,
                   const float* __restrict__ gam, const float* __restrict__ bet,
                   float* __restrict__ out)
{
    extern __shared__ float sm[];
    float* sh1 = sm;              // [64][S_H]
    float* sh2 = sm + SH2_OFF;    // [128][S_H]
    float* sI  = sm + SI_OFF;     // [64][S_I]

    const int tid  = threadIdx.x;
    const int lane = tid & 31;
    const int warp = tid >> 5;
    const int g    = blockIdx.x;

    const float2* h1v = reinterpret_cast<const float2*>(h1g) + (size_t)g * (N1 * DD / 2);
    const float2* h2v = reinterpret_cast<const float2*>(h2g) + (size_t)g * (N2 * DD / 2);
    float2* o1 = reinterpret_cast<float2*>(out) + (size_t)g * (N1 * DD);   // rows of 256 float2
    float2* o2 = reinterpret_cast<float2*>(out) + (size_t)NB * N1 * DD     // = NB*N1*2*DD/2
                                               + (size_t)g * (N2 * DD);

    // ---------------- Phase 1: global -> SMEM, fused with concat-copy halves --------------
    #pragma unroll 4
    for (int it = 0; it < (N1 * DD / 2) / 256; ++it) {   // 32 iters
        int idx = it * 256 + tid;
        int row = idx >> 7, c2 = idx & 127;
        float2 v = h1v[idx];
        *reinterpret_cast<float2*>(&sh1[row * S_H + 2 * c2]) = v;
        o1[(size_t)row * 256 + c2] = v;                  // h1_enh[:, 0:256] = h1
    }
    #pragma unroll 4
    for (int it = 0; it < (N2 * DD / 2) / 256; ++it) {   // 64 iters
        int idx = it * 256 + tid;
        int row = idx >> 7, c2 = idx & 127;
        float2 v = h2v[idx];
        *reinterpret_cast<float2*>(&sh2[row * S_H + 2 * c2]) = v;
        o2[(size_t)row * 256 + c2] = v;                  // h2_enh[:, 0:256] = h2
    }
    __syncthreads();

    // ---------------- Phase 2: GEMM1  I[64,128] = clip(h1 @ h2^T * scale) -----------------
    // 16x16 thread grid; each thread: 4 n-rows x 8 m-cols, f32x2 packed along K (d).
    {
        const int tc = tid & 15, tr = tid >> 4;
        ull acc[4][8];
        #pragma unroll
        for (int i = 0; i < 4; ++i)
            #pragma unroll
            for (int j = 0; j < 8; ++j) acc[i][j] = 0ull;

        const float* a_base = sh1 + (tr * 4) * S_H;
        const float* b_base = sh2 + tc * S_H;

        #pragma unroll 2
        for (int d = 0; d < DD; d += 2) {
            ull a2[4], b2[8];
            #pragma unroll
            for (int i = 0; i < 4; ++i) a2[i] = lds64(a_base + i * S_H + d);
            #pragma unroll
            for (int j = 0; j < 8; ++j) b2[j] = lds64(b_base + j * 16 * S_H + d);
            #pragma unroll
            for (int i = 0; i < 4; ++i)
                #pragma unroll
                for (int j = 0; j < 8; ++j)
                    acc[i][j] = fma2(a2[i], b2[j], acc[i][j]);
        }
        #pragma unroll
        for (int i = 0; i < 4; ++i) {
            #pragma unroll
            for (int j = 0; j < 8; ++j) {
                float lo, hi; unpack2(acc[i][j], lo, hi);
                float v = (lo + hi) * ISCALE;
                v = fminf(fmaxf(v, -10.0f), 10.0f);
                sI[(tr * 4 + i) * S_I + tc + 16 * j] = v;
            }
        }
    }
    __syncthreads();

    // gamma/beta for this lane's 8 columns: c = 2*lane + 64*j + {0,1}
    float gx[8], bx[8];
    {
        const float2* gv = reinterpret_cast<const float2*>(gam);
        const float2* bv = reinterpret_cast<const float2*>(bet);
        #pragma unroll
        for (int j = 0; j < 4; ++j) {
            float2 gj = gv[lane + 32 * j]; gx[2 * j] = gj.x; gx[2 * j + 1] = gj.y;
            float2 bj = bv[lane + 32 * j]; bx[2 * j] = bj.x; bx[2 * j + 1] = bj.y;
        }
    }

    // ---------------- Phase 3: GEMM2  h1_int = LN(I @ h2)  (warp-per-4-rows) --------------
    #pragma unroll 1
    for (int q = 0; q < 2; ++q) {
        const int n0 = warp * 8 + q * 4;
        ull acc[4][4];
        #pragma unroll
        for (int r = 0; r < 4; ++r)
            #pragma unroll
            for (int j = 0; j < 4; ++j) acc[r][j] = 0ull;

        const float* i_base = sI + n0 * S_I;
        #pragma unroll 4
        for (int k = 0; k < N2; k += 2) {
            ull bb0[4], bb1[4];
            #pragma unroll
            for (int j = 0; j < 4; ++j) {
                bb0[j] = lds64(sh2 + k * S_H + 2 * lane + 64 * j);
                bb1[j] = lds64(sh2 + (k + 1) * S_H + 2 * lane + 64 * j);
            }
            #pragma unroll
            for (int r = 0; r < 4; ++r) {
                float2 iv = *reinterpret_cast<const float2*>(i_base + r * S_I + k);
                ull i0 = dup2(iv.x), i1 = dup2(iv.y);
                #pragma unroll
                for (int j = 0; j < 4; ++j) {
                    acc[r][j] = fma2(i0, bb0[j], acc[r][j]);
                    acc[r][j] = fma2(i1, bb1[j], acc[r][j]);
                }
            }
        }
        #pragma unroll
        for (int r = 0; r < 4; ++r) {
            float x[8];
            #pragma unroll
            for (int j = 0; j < 4; ++j) unpack2(acc[r][j], x[2 * j], x[2 * j + 1]);
            float s = 0.f, ss = 0.f;
            #pragma unroll
            for (int i = 0; i < 8; ++i) { s += x[i]; ss += x[i] * x[i]; }
            #pragma unroll
            for (int o = 16; o; o >>= 1) {
                s  += __shfl_xor_sync(0xffffffffu, s,  o);
                ss += __shfl_xor_sync(0xffffffffu, ss, o);
            }
            float mu  = s * (1.0f / 256.0f);
            float var = ss * (1.0f / 256.0f) - mu * mu;
            float inv = rsqrtf(var + LN_EPS);
            float2* orow = o1 + (size_t)(n0 + r) * 256;
            #pragma unroll
            for (int j = 0; j < 4; ++j) {
                float2 o;
                o.x = (x[2 * j]     - mu) * inv * gx[2 * j]     + bx[2 * j];
                o.y = (x[2 * j + 1] - mu) * inv * gx[2 * j + 1] + bx[2 * j + 1];
                orow[128 + lane + 32 * j] = o;
            }
        }
    }

    // ---------------- Phase 4: GEMM3  h2_int = LN(I^T @ h1) -------------------------------
    #pragma unroll 1
    for (int q = 0; q < 4; ++q) {
        const int m0 = warp * 16 + q * 4;
        ull acc[4][4];
        #pragma unroll
        for (int r = 0; r < 4; ++r)
            #pragma unroll
            for (int j = 0; j < 4; ++j) acc[r][j] = 0ull;

        #pragma unroll 4
        for (int k = 0; k < N1; ++k) {
            ull bb[4];
            #pragma unroll
            for (int j = 0; j < 4; ++j)
                bb[j] = lds64(sh1 + k * S_H + 2 * lane + 64 * j);
            const float* ip = sI + k * S_I + m0;
            #pragma unroll
            for (int r = 0; r < 4; ++r) {
                ull ir = dup2(ip[r]);          // broadcast LDS + dup
                #pragma unroll
                for (int j = 0; j < 4; ++j)
                    acc[r][j] = fma2(ir, bb[j], acc[r][j]);
            }
        }
        #pragma unroll
        for (int r = 0; r < 4; ++r) {
            float x[8];
            #pragma unroll
            for (int j = 0; j < 4; ++j) unpack2(acc[r][j], x[2 * j], x[2 * j + 1]);
            float s = 0.f, ss = 0.f;
            #pragma unroll
            for (int i = 0; i < 8; ++i) { s += x[i]; ss += x[i] * x[i]; }
            #pragma unroll
            for (int o = 16; o; o >>= 1) {
                s  += __shfl_xor_sync(0xffffffffu, s,  o);
                ss += __shfl_xor_sync(0xffffffffu, ss, o);
            }
            float mu  = s * (1.0f / 256.0f);
            float var = ss * (1.0f / 256.0f) - mu * mu;
            float inv = rsqrtf(var + LN_EPS);
            float2* orow = o2 + (size_t)(m0 + r) * 256;
            #pragma unroll
            for (int j = 0; j < 4; ++j) {
                float2 o;
                o.x = (x[2 * j]     - mu) * inv * gx[2 * j]     + bx[2 * j];
                o.y = (x[2 * j + 1] - mu) * inv * gx[2 * j + 1] + bx[2 * j + 1];
                orow[128 + lane + 32 * j] = o;
            }
        }
    }
}

extern "C" void kernel_launch(void* const* d_in, const int* in_sizes, int n_in,
                              void* d_out, int out_size)
{
    // metadata order: h1_nodes, h2_nodes, batch1(int64, unused), batch2(int64, unused),
    //                 gamma, beta
    const float* h1  = (const float*)d_in[0];
    const float* h2  = (const float*)d_in[1];
    const float* gam = (const float*)d_in[4];
    const float* bet = (const float*)d_in[5];
    float* out = (float*)d_out;

    cudaFuncSetAttribute(interaction_kernel,
                         cudaFuncAttributeMaxDynamicSharedMemorySize, SMEM_BYTES);
    interaction_kernel<<<NB, 256, SMEM_BYTES>>>(h1, h2, gam, bet, out);
}

// round 4
// speedup vs baseline: 1.0898x; 1.0898x over previous
#include <cuda_runtime.h>
#include <cstdint>

typedef unsigned long long ull;

#define NB      1024
#define N1      64
#define N2      128
#define DD      256
#define LN_EPS  1e-5f
#define ISCALE  0.0625f     // D^-0.5 = 1/16

// SMEM strides (in floats). 258 => consecutive rows shift banks by 2 (conflict-free
// column access, 8-byte aligned for float2). 132 => conflict-free-ish I access.
#define S_H 258
#define S_I 132

static constexpr int SH2_OFF     = N1 * S_H;              // 16512 floats
static constexpr int SI_OFF      = SH2_OFF + N2 * S_H;    // 49536 floats
static constexpr int SMEM_FLOATS = SI_OFF + N1 * S_I;     // 57984 floats
static constexpr int SMEM_BYTES  = SMEM_FLOATS * 4;       // 231936 B

// ---- packed fp32x2 helpers (Blackwell FFMA2 path) ----
__device__ __forceinline__ ull fma2(ull a, ull b, ull c) {
    ull d;
    asm("fma.rn.f32x2 %0, %1, %2, %3;" : "=l"(d) : "l"(a), "l"(b), "l"(c));
    return d;
}
__device__ __forceinline__ ull dup2(float x) {
    unsigned xu = __float_as_uint(x);
    ull r;
    asm("mov.b64 %0, {%1, %1};" : "=l"(r) : "r"(xu));
    return r;
}
__device__ __forceinline__ void unpack2(ull v, float& lo, float& hi) {
    unsigned a, b;
    asm("mov.b64 {%0, %1}, %2;" : "=r"(a), "=r"(b) : "l"(v));
    lo = __uint_as_float(a);
    hi = __uint_as_float(b);
}
__device__ __forceinline__ ull lds64(const float* p) {
    return *reinterpret_cast<const ull*>(p);
}

// LayerNorm over a warp-distributed row (8 values/thread, cols c = 2*lane+64*j+{0,1})
__device__ __forceinline__ void ln_store(const ull acc[4], const float gx[8],
                                         const float bx[8], float2* orow, int lane)
{
    float x[8];
    #pragma unroll
    for (int j = 0; j < 4; ++j) unpack2(acc[j], x[2 * j], x[2 * j + 1]);
    float s = 0.f, ss = 0.f;
    #pragma unroll
    for (int i = 0; i < 8; ++i) { s += x[i]; ss += x[i] * x[i]; }
    #pragma unroll
    for (int o = 16; o; o >>= 1) {
        s  += __shfl_xor_sync(0xffffffffu, s,  o);
        ss += __shfl_xor_sync(0xffffffffu, ss, o);
    }
    float mu  = s * (1.0f / 256.0f);
    float var = ss * (1.0f / 256.0f) - mu * mu;
    float inv = rsqrtf(var + LN_EPS);
    #pragma unroll
    for (int j = 0; j < 4; ++j) {
        float2 o;
        o.x = (x[2 * j]     - mu) * inv * gx[2 * j]     + bx[2 * j];
        o.y = (x[2 * j + 1] - mu) * inv * gx[2 * j + 1] + bx[2 * j + 1];
        orow[128 + lane + 32 * j] = o;
    }
}

__global__ void __launch_bounds__(256, 1)
interaction_kernel(const float* __restrict__ h1g, const float* __restrict__ h2g,
                   const float* __restrict__ gam, const float* __restrict__ bet,
                   float* __restrict__ out)
{
    extern __shared__ float sm[];
    float* sh1 = sm;              // [64][S_H]
    float* sh2 = sm + SH2_OFF;    // [128][S_H]
    float* sI  = sm + SI_OFF;     // [64][S_I]

    const int tid  = threadIdx.x;
    const int lane = tid & 31;
    const int warp = tid >> 5;
    const int g    = blockIdx.x;

    const float4* h1v = reinterpret_cast<const float4*>(h1g) + (size_t)g * (N1 * DD / 4);
    const float4* h2v = reinterpret_cast<const float4*>(h2g) + (size_t)g * (N2 * DD / 4);
    float4* o1x = reinterpret_cast<float4*>(out) + (size_t)g * (N1 * DD / 2);   // rows of 128 float4
    float4* o2x = reinterpret_cast<float4*>(out) + (size_t)NB * (N1 * DD / 2)
                                                 + (size_t)g * (N2 * DD / 2);
    float2* o1 = reinterpret_cast<float2*>(out) + (size_t)g * (N1 * DD);
    float2* o2 = reinterpret_cast<float2*>(out) + (size_t)NB * N1 * DD
                                               + (size_t)g * (N2 * DD);

    // ---------------- Phase 1: global -> SMEM (LDG.128), fused concat-copy ----------------
    #pragma unroll 4
    for (int it = 0; it < (N1 * DD / 4) / 256; ++it) {   // 16 iters
        int idx = it * 256 + tid;
        int row = idx >> 6, c4 = idx & 63;
        float4 v = h1v[idx];
        float* d = &sh1[row * S_H + 4 * c4];
        *reinterpret_cast<float2*>(d)     = make_float2(v.x, v.y);
        *reinterpret_cast<float2*>(d + 2) = make_float2(v.z, v.w);
        o1x[(size_t)row * 128 + c4] = v;                 // h1_enh[:, 0:256] = h1
    }
    #pragma unroll 4
    for (int it = 0; it < (N2 * DD / 4) / 256; ++it) {   // 32 iters
        int idx = it * 256 + tid;
        int row = idx >> 6, c4 = idx & 63;
        float4 v = h2v[idx];
        float* d = &sh2[row * S_H + 4 * c4];
        *reinterpret_cast<float2*>(d)     = make_float2(v.x, v.y);
        *reinterpret_cast<float2*>(d + 2) = make_float2(v.z, v.w);
        o2x[(size_t)row * 128 + c4] = v;                 // h2_enh[:, 0:256] = h2
    }
    __syncthreads();

    // ---------------- Phase 2: GEMM1  I[64,128] = clip(h1 @ h2^T * scale) -----------------
    // K-split across two 128-thread groups; each thread: 8 rows x 8 cols, K packed f32x2.
    // 16 LDS.64 per 64 FFMA2 => 128 B/cyc (crossbar-balanced).
    {
        const int grp = tid >> 7;        // 0 or 1: K half
        const int t   = tid & 127;
        const int tr  = t >> 4;          // 0..7 -> rows tr*8 .. tr*8+7
        const int tc  = t & 15;          // cols tc + 16*j
        const int kb  = grp * (DD / 2);

        ull acc[8][8];
        #pragma unroll
        for (int i = 0; i < 8; ++i)
            #pragma unroll
            for (int j = 0; j < 8; ++j) acc[i][j] = 0ull;

        const float* a_base = sh1 + (tr * 8) * S_H + kb;
        const float* b_base = sh2 + tc * S_H + kb;

        #pragma unroll 1
        for (int d = 0; d < DD / 2; d += 2) {
            ull a2[8], b2[8];
            #pragma unroll
            for (int i = 0; i < 8; ++i) a2[i] = lds64(a_base + i * S_H + d);
            #pragma unroll
            for (int j = 0; j < 8; ++j) b2[j] = lds64(b_base + j * 16 * S_H + d);
            #pragma unroll
            for (int i = 0; i < 8; ++i)
                #pragma unroll
                for (int j = 0; j < 8; ++j)
                    acc[i][j] = fma2(a2[i], b2[j], acc[i][j]);
        }

        if (grp == 1) {     // store raw partials
            #pragma unroll
            for (int i = 0; i < 8; ++i)
                #pragma unroll
                for (int j = 0; j < 8; ++j) {
                    float lo, hi; unpack2(acc[i][j], lo, hi);
                    sI[(tr * 8 + i) * S_I + tc + 16 * j] = lo + hi;
                }
        }
        __syncthreads();
        if (grp == 0) {     // combine + scale + clip
            #pragma unroll
            for (int i = 0; i < 8; ++i)
                #pragma unroll
                for (int j = 0; j < 8; ++j) {
                    float lo, hi; unpack2(acc[i][j], lo, hi);
                    float v = (lo + hi + sI[(tr * 8 + i) * S_I + tc + 16 * j]) * ISCALE;
                    v = fminf(fmaxf(v, -10.0f), 10.0f);
                    sI[(tr * 8 + i) * S_I + tc + 16 * j] = v;
                }
        }
        __syncthreads();
    }

    // gamma/beta for this lane's 8 columns: c = 2*lane + 64*j + {0,1}
    float gx[8], bx[8];
    {
        const float2* gv = reinterpret_cast<const float2*>(gam);
        const float2* bv = reinterpret_cast<const float2*>(bet);
        #pragma unroll
        for (int j = 0; j < 4; ++j) {
            float2 gj = gv[lane + 32 * j]; gx[2 * j] = gj.x; gx[2 * j + 1] = gj.y;
            float2 bj = bv[lane + 32 * j]; bx[2 * j] = bj.x; bx[2 * j + 1] = bj.y;
        }
    }

    // ---------------- Phase 3: GEMM2  h1_int = LN(I @ h2)  (8 rows / warp) ----------------
    {
        const int n0 = warp * 8;
        ull acc[8][4];
        #pragma unroll
        for (int r = 0; r < 8; ++r)
            #pragma unroll
            for (int j = 0; j < 4; ++j) acc[r][j] = 0ull;

        #pragma unroll 1
        for (int k = 0; k < N2; k += 2) {
            ull bb0[4], bb1[4];
            #pragma unroll
            for (int j = 0; j < 4; ++j) {
                bb0[j] = lds64(sh2 + k * S_H + 2 * lane + 64 * j);
                bb1[j] = lds64(sh2 + (k + 1) * S_H + 2 * lane + 64 * j);
            }
            #pragma unroll
            for (int r = 0; r < 8; ++r) {
                float2 iv = *reinterpret_cast<const float2*>(sI + (n0 + r) * S_I + k);
                ull i0 = dup2(iv.x), i1 = dup2(iv.y);
                #pragma unroll
                for (int j = 0; j < 4; ++j) {
                    acc[r][j] = fma2(i0, bb0[j], acc[r][j]);
                    acc[r][j] = fma2(i1, bb1[j], acc[r][j]);
                }
            }
        }
        #pragma unroll
        for (int r = 0; r < 8; ++r)
            ln_store(acc[r], gx, bx, o1 + (size_t)(n0 + r) * 256, lane);
    }

    // ---------------- Phase 4: GEMM3  h2_int = LN(I^T @ h1)  (8 rows / warp x2) -----------
    #pragma unroll 1
    for (int q = 0; q < 2; ++q) {
        const int m0 = warp * 16 + q * 8;
        ull acc[8][4];
        #pragma unroll
        for (int r = 0; r < 8; ++r)
            #pragma unroll
            for (int j = 0; j < 4; ++j) acc[r][j] = 0ull;

        #pragma unroll 1
        for (int k = 0; k < N1; k += 2) {
            ull bb0[4], bb1[4];
            #pragma unroll
            for (int j = 0; j < 4; ++j) {
                bb0[j] = lds64(sh1 + k * S_H + 2 * lane + 64 * j);
                bb1[j] = lds64(sh1 + (k + 1) * S_H + 2 * lane + 64 * j);
            }
            // I[k, m0..m0+7] and I[k+1, m0..m0+7]: contiguous -> float4 broadcast loads
            float4 iA0 = *reinterpret_cast<const float4*>(sI + k * S_I + m0);
            float4 iA1 = *reinterpret_cast<const float4*>(sI + k * S_I + m0 + 4);
            float4 iB0 = *reinterpret_cast<const float4*>(sI + (k + 1) * S_I + m0);
            float4 iB1 = *reinterpret_cast<const float4*>(sI + (k + 1) * S_I + m0 + 4);
            float ia[8] = {iA0.x, iA0.y, iA0.z, iA0.w, iA1.x, iA1.y, iA1.z, iA1.w};
            float ib[8] = {iB0.x, iB0.y, iB0.z, iB0.w, iB1.x, iB1.y, iB1.z, iB1.w};
            #pragma unroll
            for (int r = 0; r < 8; ++r) {
                ull i0 = dup2(ia[r]), i1 = dup2(ib[r]);
                #pragma unroll
                for (int j = 0; j < 4; ++j) {
                    acc[r][j] = fma2(i0, bb0[j], acc[r][j]);
                    acc[r][j] = fma2(i1, bb1[j], acc[r][j]);
                }
            }
        }
        #pragma unroll
        for (int r = 0; r < 8; ++r)
            ln_store(acc[r], gx, bx, o2 + (size_t)(m0 + r) * 256, lane);
    }
}

extern "C" void kernel_launch(void* const* d_in, const int* in_sizes, int n_in,
                              void* d_out, int out_size)
{
    // metadata order: h1_nodes, h2_nodes, batch1(int64, unused), batch2(int64, unused),
    //                 gamma, beta
    const float* h1  = (const float*)d_in[0];
    const float* h2  = (const float*)d_in[1];
    const float* gam = (const float*)d_in[4];
    const float* bet = (const float*)d_in[5];
    float* out = (float*)d_out;

    cudaFuncSetAttribute(interaction_kernel,
                         cudaFuncAttributeMaxDynamicSharedMemorySize, SMEM_BYTES);
    interaction_kernel<<<NB, 256, SMEM_BYTES>>>(h1, h2, gam, bet, out);
}

// round 5
// speedup vs baseline: 1.1492x; 1.0545x over previous
#include <cuda_runtime.h>
#include <cstdint>

typedef unsigned long long ull;

#define NB      1024
#define N1      64
#define N2      128
#define DD      256
#define LN_EPS  1e-5f
#define ISCALE  0.0625f     // D^-0.5 = 1/16
#define NT      512

// SMEM strides (in floats). 258 => consecutive rows shift banks by 2 (conflict-free
// column access, 8-byte aligned for float2). 132 => conflict-free-ish I access.
#define S_H 258
#define S_I 132

static constexpr int SH2_OFF     = N1 * S_H;              // 16512 floats
static constexpr int SI_OFF      = SH2_OFF + N2 * S_H;    // 49536 floats
static constexpr int SMEM_FLOATS = SI_OFF + N1 * S_I;     // 57984 floats
static constexpr int SMEM_BYTES  = SMEM_FLOATS * 4;       // 231936 B

// ---- packed fp32x2 helpers (Blackwell FFMA2 path) ----
__device__ __forceinline__ ull fma2(ull a, ull b, ull c) {
    ull d;
    asm("fma.rn.f32x2 %0, %1, %2, %3;" : "=l"(d) : "l"(a), "l"(b), "l"(c));
    return d;
}
__device__ __forceinline__ ull dup2(float x) {
    unsigned xu = __float_as_uint(x);
    ull r;
    asm("mov.b64 %0, {%1, %1};" : "=l"(r) : "r"(xu));
    return r;
}
__device__ __forceinline__ void unpack2(ull v, float& lo, float& hi) {
    unsigned a, b;
    asm("mov.b64 {%0, %1}, %2;" : "=r"(a), "=r"(b) : "l"(v));
    lo = __uint_as_float(a);
    hi = __uint_as_float(b);
}
__device__ __forceinline__ ull lds64(const float* p) {
    return *reinterpret_cast<const ull*>(p);
}

// LayerNorm over a warp-distributed row (8 values/thread, cols c = 2*lane+64*j+{0,1})
__device__ __forceinline__ void ln_store(const ull acc[4], const float gx[8],
                                         const float bx[8], float2* orow, int lane)
{
    float x[8];
    #pragma unroll
    for (int j = 0; j < 4; ++j) unpack2(acc[j], x[2 * j], x[2 * j + 1]);
    float s = 0.f, ss = 0.f;
    #pragma unroll
    for (int i = 0; i < 8; ++i) { s += x[i]; ss += x[i] * x[i]; }
    #pragma unroll
    for (int o = 16; o; o >>= 1) {
        s  += __shfl_xor_sync(0xffffffffu, s,  o);
        ss += __shfl_xor_sync(0xffffffffu, ss, o);
    }
    float mu  = s * (1.0f / 256.0f);
    float var = ss * (1.0f / 256.0f) - mu * mu;
    float inv = rsqrtf(var + LN_EPS);
    #pragma unroll
    for (int j = 0; j < 4; ++j) {
        float2 o;
        o.x = (x[2 * j]     - mu) * inv * gx[2 * j]     + bx[2 * j];
        o.y = (x[2 * j + 1] - mu) * inv * gx[2 * j + 1] + bx[2 * j + 1];
        orow[128 + lane + 32 * j] = o;
    }
}

__global__ void __launch_bounds__(NT, 1)
interaction_kernel(const float* __restrict__ h1g, const float* __restrict__ h2g,
                   const float* __restrict__ gam, const float* __restrict__ bet,
                   float* __restrict__ out)
{
    extern __shared__ float sm[];
    float* sh1 = sm;              // [64][S_H]
    float* sh2 = sm + SH2_OFF;    // [128][S_H]
    float* sI  = sm + SI_OFF;     // [64][S_I]

    const int tid  = threadIdx.x;
    const int lane = tid & 31;
    const int warp = tid >> 5;    // 0..15
    const int g    = blockIdx.x;

    const float4* h1v = reinterpret_cast<const float4*>(h1g) + (size_t)g * (N1 * DD / 4);
    const float4* h2v = reinterpret_cast<const float4*>(h2g) + (size_t)g * (N2 * DD / 4);
    float4* o1x = reinterpret_cast<float4*>(out) + (size_t)g * (N1 * DD / 2);   // rows of 128 float4
    float4* o2x = reinterpret_cast<float4*>(out) + (size_t)NB * (N1 * DD / 2)
                                                 + (size_t)g * (N2 * DD / 2);
    float2* o1 = reinterpret_cast<float2*>(out) + (size_t)g * (N1 * DD);
    float2* o2 = reinterpret_cast<float2*>(out) + (size_t)NB * N1 * DD
                                               + (size_t)g * (N2 * DD);

    // ---------------- Phase 1: global -> SMEM (LDG.128), fused concat-copy ----------------
    #pragma unroll 4
    for (int it = 0; it < (N1 * DD / 4) / NT; ++it) {    // 8 iters
        int idx = it * NT + tid;
        int row = idx >> 6, c4 = idx & 63;
        float4 v = h1v[idx];
        float* d = &sh1[row * S_H + 4 * c4];
        *reinterpret_cast<float2*>(d)     = make_float2(v.x, v.y);
        *reinterpret_cast<float2*>(d + 2) = make_float2(v.z, v.w);
        o1x[(size_t)row * 128 + c4] = v;                 // h1_enh[:, 0:256] = h1
    }
    #pragma unroll 4
    for (int it = 0; it < (N2 * DD / 4) / NT; ++it) {    // 16 iters
        int idx = it * NT + tid;
        int row = idx >> 6, c4 = idx & 63;
        float4 v = h2v[idx];
        float* d = &sh2[row * S_H + 4 * c4];
        *reinterpret_cast<float2*>(d)     = make_float2(v.x, v.y);
        *reinterpret_cast<float2*>(d + 2) = make_float2(v.z, v.w);
        o2x[(size_t)row * 128 + c4] = v;                 // h2_enh[:, 0:256] = h2
    }
    __syncthreads();

    // ---------------- Phase 2: GEMM1  I[64,128] = clip(h1 @ h2^T * scale) -----------------
    // K-split across two 256-thread groups; each thread: 4 rows x 8 cols, K packed f32x2.
    {
        const int grp = tid >> 8;        // 0 or 1: K half
        const int t   = tid & 255;
        const int tr  = t >> 4;          // 0..15 -> rows tr*4 .. tr*4+3
        const int tc  = t & 15;          // cols tc + 16*j
        const int kb  = grp * (DD / 2);

        ull acc[4][8];
        #pragma unroll
        for (int i = 0; i < 4; ++i)
            #pragma unroll
            for (int j = 0; j < 8; ++j) acc[i][j] = 0ull;

        const float* a_base = sh1 + (tr * 4) * S_H + kb;
        const float* b_base = sh2 + tc * S_H + kb;

        #pragma unroll 1
        for (int d = 0; d < DD / 2; d += 2) {
            ull a2[4], b2[8];
            #pragma unroll
            for (int i = 0; i < 4; ++i) a2[i] = lds64(a_base + i * S_H + d);
            #pragma unroll
            for (int j = 0; j < 8; ++j) b2[j] = lds64(b_base + j * 16 * S_H + d);
            #pragma unroll
            for (int i = 0; i < 4; ++i)
                #pragma unroll
                for (int j = 0; j < 8; ++j)
                    acc[i][j] = fma2(a2[i], b2[j], acc[i][j]);
        }

        if (grp == 1) {     // store raw partials
            #pragma unroll
            for (int i = 0; i < 4; ++i)
                #pragma unroll
                for (int j = 0; j < 8; ++j) {
                    float lo, hi; unpack2(acc[i][j], lo, hi);
                    sI[(tr * 4 + i) * S_I + tc + 16 * j] = lo + hi;
                }
        }
        __syncthreads();
        if (grp == 0) {     // combine + scale + clip
            #pragma unroll
            for (int i = 0; i < 4; ++i)
                #pragma unroll
                for (int j = 0; j < 8; ++j) {
                    float lo, hi; unpack2(acc[i][j], lo, hi);
                    float v = (lo + hi + sI[(tr * 4 + i) * S_I + tc + 16 * j]) * ISCALE;
                    v = fminf(fmaxf(v, -10.0f), 10.0f);
                    sI[(tr * 4 + i) * S_I + tc + 16 * j] = v;
                }
        }
        __syncthreads();
    }

    // gamma/beta for this lane's 8 columns: c = 2*lane + 64*j + {0,1}
    float gx[8], bx[8];
    {
        const float2* gv = reinterpret_cast<const float2*>(gam);
        const float2* bv = reinterpret_cast<const float2*>(bet);
        #pragma unroll
        for (int j = 0; j < 4; ++j) {
            float2 gj = gv[lane + 32 * j]; gx[2 * j] = gj.x; gx[2 * j + 1] = gj.y;
            float2 bj = bv[lane + 32 * j]; bx[2 * j] = bj.x; bx[2 * j + 1] = bj.y;
        }
    }

    // ---------------- Phase 3: GEMM2  h1_int = LN(I @ h2)  (4 rows / warp) ----------------
    {
        const int n0 = warp * 4;
        ull acc[4][4];
        #pragma unroll
        for (int r = 0; r < 4; ++r)
            #pragma unroll
            for (int j = 0; j < 4; ++j) acc[r][j] = 0ull;

        #pragma unroll 1
        for (int k = 0; k < N2; k += 2) {
            ull bb0[4], bb1[4];
            #pragma unroll
            for (int j = 0; j < 4; ++j) {
                bb0[j] = lds64(sh2 + k * S_H + 2 * lane + 64 * j);
                bb1[j] = lds64(sh2 + (k + 1) * S_H + 2 * lane + 64 * j);
            }
            #pragma unroll
            for (int r = 0; r < 4; ++r) {
                float2 iv = *reinterpret_cast<const float2*>(sI + (n0 + r) * S_I + k);
                ull i0 = dup2(iv.x), i1 = dup2(iv.y);
                #pragma unroll
                for (int j = 0; j < 4; ++j) {
                    acc[r][j] = fma2(i0, bb0[j], acc[r][j]);
                    acc[r][j] = fma2(i1, bb1[j], acc[r][j]);
                }
            }
        }
        #pragma unroll
        for (int r = 0; r < 4; ++r)
            ln_store(acc[r], gx, bx, o1 + (size_t)(n0 + r) * 256, lane);
    }

    // ---------------- Phase 4: GEMM3  h2_int = LN(I^T @ h1)  (8 rows / warp) --------------
    {
        const int m0 = warp * 8;
        ull acc[8][4];
        #pragma unroll
        for (int r = 0; r < 8; ++r)
            #pragma unroll
            for (int j = 0; j < 4; ++j) acc[r][j] = 0ull;

        #pragma unroll 1
        for (int k = 0; k < N1; k += 2) {
            ull bb0[4], bb1[4];
            #pragma unroll
            for (int j = 0; j < 4; ++j) {
                bb0[j] = lds64(sh1 + k * S_H + 2 * lane + 64 * j);
                bb1[j] = lds64(sh1 + (k + 1) * S_H + 2 * lane + 64 * j);
            }
            // I[k, m0..m0+7] and I[k+1, m0..m0+7]: contiguous -> float4 broadcast loads
            float4 iA0 = *reinterpret_cast<const float4*>(sI + k * S_I + m0);
            float4 iA1 = *reinterpret_cast<const float4*>(sI + k * S_I + m0 + 4);
            float4 iB0 = *reinterpret_cast<const float4*>(sI + (k + 1) * S_I + m0);
            float4 iB1 = *reinterpret_cast<const float4*>(sI + (k + 1) * S_I + m0 + 4);
            float ia[8] = {iA0.x, iA0.y, iA0.z, iA0.w, iA1.x, iA1.y, iA1.z, iA1.w};
            float ib[8] = {iB0.x, iB0.y, iB0.z, iB0.w, iB1.x, iB1.y, iB1.z, iB1.w};
            #pragma unroll
            for (int r = 0; r < 8; ++r) {
                ull i0 = dup2(ia[r]), i1 = dup2(ib[r]);
                #pragma unroll
                for (int j = 0; j < 4; ++j) {
                    acc[r][j] = fma2(i0, bb0[j], acc[r][j]);
                    acc[r][j] = fma2(i1, bb1[j], acc[r][j]);
                }
            }
        }
        #pragma unroll
        for (int r = 0; r < 8; ++r)
            ln_store(acc[r], gx, bx, o2 + (size_t)(m0 + r) * 256, lane);
    }
}

extern "C" void kernel_launch(void* const* d_in, const int* in_sizes, int n_in,
                              void* d_out, int out_size)
{
    // metadata order: h1_nodes, h2_nodes, batch1(int64, unused), batch2(int64, unused),
    //                 gamma, beta
    const float* h1  = (const float*)d_in[0];
    const float* h2  = (const float*)d_in[1];
    const float* gam = (const float*)d_in[4];
    const float* bet = (const float*)d_in[5];
    float* out = (float*)d_out;

    cudaFuncSetAttribute(interaction_kernel,
                         cudaFuncAttributeMaxDynamicSharedMemorySize, SMEM_BYTES);
    interaction_kernel<<<NB, NT, SMEM_BYTES>>>(h1, h2, gam, bet, out);
}